// round 10
// baseline (speedup 1.0000x reference)
#include <cuda_runtime.h>

// ---------------- problem constants ----------------
#define BB    32
#define CC    256
#define NN    1024          // H*W = 32*32
#define KD    16            // dim_depth
#define NHEAD 4
#define VV    64
#define RR    23
#define PADR  11
#define PS    54            // 32 + 2*11
#define PIMG  (PS*PS)       // 2916
#define OFFS  (RR*RR)       // 529
#define OCH   144           // 64 q + 16 k + 64 v
#define EPSBN 1e-5f

typedef unsigned long long u64;

// ---------------- scratch (device globals; no allocation) ----------------
__device__ float g_Wcat[OCH * CC];               // packed projection weights
__device__ u64   g_w2[OFFS * 8];                 // embedding packed as (k2,k2+1) f32x2 pairs
__device__ float g_proj[BB * OCH * NN];          // raw projections      18.9 MB
__device__ float g_scale[128];                   // BN scale (q:0-63, v:64-127)
__device__ float g_shift[128];                   // BN shift
__device__ float g_soft[BB * KD * NN];           // softmax(k)            2 MB
__device__ float g_qbn[BB * 64 * NN];            // normalized queries   8.4 MB
__device__ float g_vpad[BB * VV * PIMG];         // padded norm. values 23.9 MB
__device__ float g_lc[BB * KD * VV];             // lambda_c

// ---------------- small PTX helpers (packed f32x2) ----------------
__device__ __forceinline__ u64 pack2s(float x) {
    u64 r; asm("mov.b64 %0, {%1, %1};" : "=l"(r) : "f"(x)); return r;
}
__device__ __forceinline__ u64 pack2(float x, float y) {
    u64 r; asm("mov.b64 %0, {%1, %2};" : "=l"(r) : "f"(x), "f"(y)); return r;
}
__device__ __forceinline__ void unpack2(u64 r, float& lo, float& hi) {
    asm("mov.b64 {%0, %1}, %2;" : "=f"(lo), "=f"(hi) : "l"(r));
}
__device__ __forceinline__ void fma2(u64& acc, u64 a, u64 b) {
    asm("fma.rn.f32x2 %0, %1, %2, %0;" : "+l"(acc) : "l"(a), "l"(b));
}

// ================= kernel 0: pack weights =================
__global__ void pack_kernel(const float* __restrict__ Wq,
                            const float* __restrict__ Wk,
                            const float* __restrict__ Wv,
                            const float* __restrict__ emb) {
    int t = blockIdx.x * blockDim.x + threadIdx.x;
    int stride = gridDim.x * blockDim.x;
    for (int i = t; i < OCH * CC; i += stride) {
        int ch = i / CC, c = i % CC;
        float w;
        if (ch < 64)       w = Wq[ch * CC + c];
        else if (ch < 80)  w = Wk[(ch - 64) * CC + c];
        else               w = Wv[(ch - 80) * CC + c];
        g_Wcat[i] = w;
    }
    for (int i = t; i < OFFS * 8; i += stride) {
        int o = i >> 3, kk = i & 7;
        g_w2[i] = pack2(emb[(2 * kk) * OFFS + o], emb[(2 * kk + 1) * OFFS + o]);
    }
}

// ================= kernel 1: fused projection GEMM =================
// proj[b][144][1024] = Wcat[144][256] @ x[b][256][1024]
__global__ __launch_bounds__(256) void proj_kernel(const float* __restrict__ x) {
    __shared__ float xs[32][128];
    __shared__ float ws[144][32];
    int b = blockIdx.y;
    int n0 = blockIdx.x * 128;
    int tid = threadIdx.x;
    int tn = tid & 15;          // 16 n-groups
    int to = tid >> 4;          // 16 ch-groups of 9

    float acc[9][8];
    #pragma unroll
    for (int a = 0; a < 9; a++)
        #pragma unroll
        for (int e = 0; e < 8; e++) acc[a][e] = 0.f;

    for (int cb = 0; cb < 8; cb++) {
        // stage x tile: 32 c-rows x 128 n
        #pragma unroll
        for (int j = 0; j < 16; j++) {
            int f = tid + 256 * j;
            int cr = f >> 7, nn = f & 127;
            xs[cr][nn] = x[(b * CC + cb * 32 + cr) * NN + n0 + nn];
        }
        // stage weights: 144 x 32 = 4608 = 256*18
        #pragma unroll
        for (int j = 0; j < 18; j++) {
            int f = tid + 256 * j;
            int ch = f >> 5, c = f & 31;
            ws[ch][c] = g_Wcat[ch * CC + cb * 32 + c];
        }
        __syncthreads();
        #pragma unroll 4
        for (int cc = 0; cc < 32; cc++) {
            float xv[8], wv[9];
            #pragma unroll
            for (int e = 0; e < 8; e++) xv[e] = xs[cc][tn + 16 * e];
            #pragma unroll
            for (int a = 0; a < 9; a++) wv[a] = ws[to * 9 + a][cc];
            #pragma unroll
            for (int a = 0; a < 9; a++)
                #pragma unroll
                for (int e = 0; e < 8; e++) acc[a][e] = fmaf(wv[a], xv[e], acc[a][e]);
        }
        __syncthreads();
    }
    #pragma unroll
    for (int a = 0; a < 9; a++)
        #pragma unroll
        for (int e = 0; e < 8; e++)
            g_proj[(b * OCH + to * 9 + a) * NN + n0 + tn + 16 * e] = acc[a][e];
}

// ================= kernel 2: BN batch stats =================
__global__ void bnstats_kernel(const float* __restrict__ bnqw, const float* __restrict__ bnqb,
                               const float* __restrict__ bnvw, const float* __restrict__ bnvb) {
    int ch = blockIdx.x;                       // 0..127
    int src = (ch < 64) ? ch : ch + 16;        // v channels live at 80..143
    int tid = threadIdx.x;
    float s1 = 0.f, s2 = 0.f;
    for (int i = tid; i < BB * NN; i += 256) {
        int b = i >> 10, n = i & 1023;
        float v = g_proj[(b * OCH + src) * NN + n];
        s1 += v; s2 += v * v;
    }
    __shared__ float r1[256], r2[256];
    r1[tid] = s1; r2[tid] = s2;
    __syncthreads();
    for (int s = 128; s > 0; s >>= 1) {
        if (tid < s) { r1[tid] += r1[tid + s]; r2[tid] += r2[tid + s]; }
        __syncthreads();
    }
    if (tid == 0) {
        const float inv = 1.0f / (BB * NN);
        float mean = r1[0] * inv;
        float var  = r2[0] * inv - mean * mean;
        float w  = (ch < 64) ? bnqw[ch] : bnvw[ch - 64];
        float bi = (ch < 64) ? bnqb[ch] : bnvb[ch - 64];
        float sc = w * rsqrtf(var + EPSBN);
        g_scale[ch] = sc;
        g_shift[ch] = bi - mean * sc;
    }
}

// ================= kernel 3: softmax over n per (b,k) =================
__global__ __launch_bounds__(256) void softmax_kernel() {
    int row = blockIdx.x;                      // 0..511
    int b = row >> 4, k = row & 15;
    const float* src = g_proj + (b * OCH + 64 + k) * NN;
    int tid = threadIdx.x;
    float v[4];
    #pragma unroll
    for (int j = 0; j < 4; j++) v[j] = src[tid + 256 * j];
    float m = fmaxf(fmaxf(v[0], v[1]), fmaxf(v[2], v[3]));
    __shared__ float red[256];
    red[tid] = m; __syncthreads();
    for (int s = 128; s > 0; s >>= 1) {
        if (tid < s) red[tid] = fmaxf(red[tid], red[tid + s]);
        __syncthreads();
    }
    m = red[0];
    __syncthreads();
    float e[4], loc = 0.f;
    #pragma unroll
    for (int j = 0; j < 4; j++) { e[j] = expf(v[j] - m); loc += e[j]; }
    red[tid] = loc; __syncthreads();
    for (int s = 128; s > 0; s >>= 1) {
        if (tid < s) red[tid] += red[tid + s];
        __syncthreads();
    }
    float inv = 1.0f / red[0];
    float* dst = g_soft + (b * KD + k) * NN;
    #pragma unroll
    for (int j = 0; j < 4; j++) dst[tid + 256 * j] = e[j] * inv;
}

// ================= kernel 4: normalize q, normalize+pad v =================
__global__ __launch_bounds__(256) void normpad_kernel() {
    int ch = blockIdx.x, b = blockIdx.y, tid = threadIdx.x;
    float qs = g_scale[ch], qh = g_shift[ch];
    const float* qsrc = g_proj + (b * OCH + ch) * NN;
    float* qdst = g_qbn + (b * 64 + ch) * NN;
    for (int n = tid; n < NN; n += 256) qdst[n] = qsrc[n] * qs + qh;

    float vs = g_scale[64 + ch], vh = g_shift[64 + ch];
    const float* vsrc = g_proj + (b * OCH + 80 + ch) * NN;
    float* vdst = g_vpad + (b * 64 + ch) * PIMG;
    for (int i = tid; i < PIMG; i += 256) {
        int rr = i / PS, cc = i % PS;
        float val = 0.f;
        if (rr >= PADR && rr < PADR + 32 && cc >= PADR && cc < PADR + 32)
            val = vsrc[(rr - PADR) * 32 + (cc - PADR)] * vs + vh;
        vdst[i] = val;
    }
}

// ================= kernel 5: lambda_c[b,k,v] = sum_n soft * v_bn =================
__global__ __launch_bounds__(256) void lambdac_kernel() {
    int b = blockIdx.x, tid = threadIdx.x;
    int v = tid & 63;
    int kg = tid >> 6;                         // 0..3; covers k = kg + 4a
    __shared__ float ss[16][128];
    __shared__ float vsm[64][129];
    float acc[4] = {0.f, 0.f, 0.f, 0.f};
    for (int nc = 0; nc < 8; nc++) {
        int n0 = nc * 128;
        #pragma unroll
        for (int j = 0; j < 8; j++) {
            int f = tid + 256 * j;
            int k = f >> 7, n = f & 127;
            ss[k][n] = g_soft[(b * KD + k) * NN + n0 + n];
        }
        #pragma unroll
        for (int j = 0; j < 32; j++) {
            int f = tid + 256 * j;
            int vv = f >> 7, n = f & 127;
            int nn = n0 + n;
            vsm[vv][n] = g_vpad[(b * 64 + vv) * PIMG + ((nn >> 5) + PADR) * PS + (nn & 31) + PADR];
        }
        __syncthreads();
        for (int n = 0; n < 128; n++) {
            float vx = vsm[v][n];
            #pragma unroll
            for (int a = 0; a < 4; a++) acc[a] = fmaf(ss[kg + 4 * a][n], vx, acc[a]);
        }
        __syncthreads();
    }
    #pragma unroll
    for (int a = 0; a < 4; a++) g_lc[(b * KD + kg + 4 * a) * VV + v] = acc[a];
}

// ================= kernel 6: fused conv(lambda_p) + y_p + y_c + output =================
__global__ __launch_bounds__(256) void main_kernel(const float* __restrict__ gamma,
                                                   float* __restrict__ out) {
    __shared__ float img[PIMG];                // 11664 B
    __shared__ ulonglong2 w2sm[OFFS * 4];      // 33856 B  (8 k-pairs per offset)
    __shared__ float lcs[16];

    int v = blockIdx.x, b = blockIdx.y;
    int tid = threadIdx.x;
    int c  = tid & 31;
    int r0 = tid >> 5;                         // 0..7; pixels at rows r0+8i

    const float* imsrc = g_vpad + (b * 64 + v) * PIMG;
    for (int i = tid; i < PIMG; i += 256) img[i] = imsrc[i];
    {
        u64* wdst = reinterpret_cast<u64*>(w2sm);
        for (int i = tid; i < OFFS * 8; i += 256) wdst[i] = g_w2[i];
    }
    if (tid < 16) lcs[tid] = g_lc[(b * KD + tid) * VV + v];
    __syncthreads();

    u64 acc[4][8];
    #pragma unroll
    for (int i = 0; i < 4; i++)
        #pragma unroll
        for (int kk = 0; kk < 8; kk++) acc[i][kk] = 0ull;

    for (int dr = 0; dr < RR; dr++) {
        const float* irow = img + (r0 + dr) * PS + c;
        const ulonglong2* wrow = w2sm + dr * RR * 4;
        #pragma unroll 1
        for (int dc = 0; dc < RR; dc++) {
            u64 vv0 = pack2s(irow[dc]);
            u64 vv1 = pack2s(irow[dc + 8 * PS]);
            u64 vv2 = pack2s(irow[dc + 16 * PS]);
            u64 vv3 = pack2s(irow[dc + 24 * PS]);
            const ulonglong2* wo = wrow + dc * 4;
            #pragma unroll
            for (int j = 0; j < 4; j++) {
                ulonglong2 wp = wo[j];
                fma2(acc[0][2 * j],     wp.x, vv0);
                fma2(acc[1][2 * j],     wp.x, vv1);
                fma2(acc[2][2 * j],     wp.x, vv2);
                fma2(acc[3][2 * j],     wp.x, vv3);
                fma2(acc[0][2 * j + 1], wp.y, vv0);
                fma2(acc[1][2 * j + 1], wp.y, vv1);
                fma2(acc[2][2 * j + 1], wp.y, vv2);
                fma2(acc[3][2 * j + 1], wp.y, vv3);
            }
        }
    }

    // epilogue: lam_tot[k] = lambda_p + lambda_c;  out = (1+g) * sum_k q * lam_tot
    float g1 = 1.0f + gamma[0];
    #pragma unroll
    for (int i = 0; i < 4; i++) {
        float lam[16];
        #pragma unroll
        for (int kk = 0; kk < 8; kk++) {
            float lo, hi;
            unpack2(acc[i][kk], lo, hi);
            lam[2 * kk]     = lo + lcs[2 * kk];
            lam[2 * kk + 1] = hi + lcs[2 * kk + 1];
        }
        int n = (r0 + 8 * i) * 32 + c;
        const float* qb = g_qbn + (b * 64) * NN + n;
        #pragma unroll
        for (int h = 0; h < 4; h++) {
            float y = 0.f;
            #pragma unroll
            for (int k = 0; k < 16; k++)
                y = fmaf(qb[(h * 16 + k) * NN], lam[k], y);
            out[((b * 256) + h * 64 + v) * NN + n] = g1 * y;
        }
    }
}

// ================= launch =================
extern "C" void kernel_launch(void* const* d_in, const int* in_sizes, int n_in,
                              void* d_out, int out_size) {
    (void)in_sizes; (void)n_in; (void)out_size;
    const float* x    = (const float*)d_in[0];
    const float* Wq   = (const float*)d_in[1];
    const float* bnqw = (const float*)d_in[2];
    const float* bnqb = (const float*)d_in[3];
    const float* Wk   = (const float*)d_in[4];
    const float* Wv   = (const float*)d_in[5];
    const float* bnvw = (const float*)d_in[6];
    const float* bnvb = (const float*)d_in[7];
    const float* emb  = (const float*)d_in[8];
    const float* gam  = (const float*)d_in[9];
    float* out = (float*)d_out;

    pack_kernel<<<32, 256>>>(Wq, Wk, Wv, emb);
    proj_kernel<<<dim3(8, 32), 256>>>(x);
    bnstats_kernel<<<128, 256>>>(bnqw, bnqb, bnvw, bnvb);
    softmax_kernel<<<512, 256>>>();
    normpad_kernel<<<dim3(64, 32), 256>>>();
    lambdac_kernel<<<32, 256>>>();
    main_kernel<<<dim3(64, 32), 256>>>(gam, out);
}

// round 16
// speedup vs baseline: 1.0177x; 1.0177x over previous
#include <cuda_runtime.h>

// ---------------- problem constants ----------------
#define BB    32
#define CC    256
#define NN    1024          // H*W = 32*32
#define KD    16            // dim_depth
#define NHEAD 4
#define VV    64
#define RR    23
#define PADR  11
#define PS    54            // 32 + 2*11
#define PIMG  (PS*PS)       // 2916
#define OFFS  (RR*RR)       // 529
#define OCH   144           // 64 q + 16 k + 64 v
#define EPSBN 1e-5f

typedef unsigned long long u64;

// ---------------- scratch (device globals; no allocation) ----------------
__device__ float g_Wcat[OCH * CC];               // packed projection weights
__device__ float g_proj[BB * OCH * NN];          // raw projections      18.9 MB
__device__ float g_scale[128];                   // BN scale (q:0-63, v:64-127)
__device__ float g_shift[128];                   // BN shift
__device__ float g_soft[BB * KD * NN];           // softmax(k)            2 MB
__device__ float g_qbn[BB * 64 * NN];            // normalized queries   8.4 MB
__device__ float g_vpad[BB * VV * PIMG];         // padded norm. values 23.9 MB
__device__ float g_lc[BB * KD * VV];             // lambda_c
__device__ float g_qt[BB * NHEAD * OFFS * NN];   // Q-tilde [b][h][o][n]  277 MB

// ---------------- small PTX helpers (packed f32x2) ----------------
__device__ __forceinline__ u64 pack2s(float x) {
    u64 r; asm("mov.b64 %0, {%1, %1};" : "=l"(r) : "f"(x)); return r;
}
__device__ __forceinline__ u64 pack2(float x, float y) {
    u64 r; asm("mov.b64 %0, {%1, %2};" : "=l"(r) : "f"(x), "f"(y)); return r;
}
__device__ __forceinline__ void unpack2(u64 r, float& lo, float& hi) {
    asm("mov.b64 {%0, %1}, %2;" : "=f"(lo), "=f"(hi) : "l"(r));
}
__device__ __forceinline__ void fma2(u64& acc, u64 a, u64 b) {
    asm("fma.rn.f32x2 %0, %1, %2, %0;" : "+l"(acc) : "l"(a), "l"(b));
}

// ================= kernel 0: pack projection weights =================
__global__ void pack_kernel(const float* __restrict__ Wq,
                            const float* __restrict__ Wk,
                            const float* __restrict__ Wv) {
    int t = blockIdx.x * blockDim.x + threadIdx.x;
    int stride = gridDim.x * blockDim.x;
    for (int i = t; i < OCH * CC; i += stride) {
        int ch = i / CC, c = i % CC;
        float w;
        if (ch < 64)       w = Wq[ch * CC + c];
        else if (ch < 80)  w = Wk[(ch - 64) * CC + c];
        else               w = Wv[(ch - 80) * CC + c];
        g_Wcat[i] = w;
    }
}

// ================= kernel 1: fused projection GEMM =================
// proj[b][144][1024] = Wcat[144][256] @ x[b][256][1024]
__global__ __launch_bounds__(256) void proj_kernel(const float* __restrict__ x) {
    __shared__ float xs[32][128];
    __shared__ float ws[144][32];
    int b = blockIdx.y;
    int n0 = blockIdx.x * 128;
    int tid = threadIdx.x;
    int tn = tid & 15;          // 16 n-groups
    int to = tid >> 4;          // 16 ch-groups of 9

    float acc[9][8];
    #pragma unroll
    for (int a = 0; a < 9; a++)
        #pragma unroll
        for (int e = 0; e < 8; e++) acc[a][e] = 0.f;

    for (int cb = 0; cb < 8; cb++) {
        #pragma unroll
        for (int j = 0; j < 16; j++) {
            int f = tid + 256 * j;
            int cr = f >> 7, nn = f & 127;
            xs[cr][nn] = x[(b * CC + cb * 32 + cr) * NN + n0 + nn];
        }
        #pragma unroll
        for (int j = 0; j < 18; j++) {
            int f = tid + 256 * j;
            int ch = f >> 5, c = f & 31;
            ws[ch][c] = g_Wcat[ch * CC + cb * 32 + c];
        }
        __syncthreads();
        #pragma unroll 4
        for (int cc = 0; cc < 32; cc++) {
            float xv[8], wv[9];
            #pragma unroll
            for (int e = 0; e < 8; e++) xv[e] = xs[cc][tn + 16 * e];
            #pragma unroll
            for (int a = 0; a < 9; a++) wv[a] = ws[to * 9 + a][cc];
            #pragma unroll
            for (int a = 0; a < 9; a++)
                #pragma unroll
                for (int e = 0; e < 8; e++) acc[a][e] = fmaf(wv[a], xv[e], acc[a][e]);
        }
        __syncthreads();
    }
    #pragma unroll
    for (int a = 0; a < 9; a++)
        #pragma unroll
        for (int e = 0; e < 8; e++)
            g_proj[(b * OCH + to * 9 + a) * NN + n0 + tn + 16 * e] = acc[a][e];
}

// ================= kernel 2: BN batch stats =================
__global__ void bnstats_kernel(const float* __restrict__ bnqw, const float* __restrict__ bnqb,
                               const float* __restrict__ bnvw, const float* __restrict__ bnvb) {
    int ch = blockIdx.x;                       // 0..127
    int src = (ch < 64) ? ch : ch + 16;        // v channels live at 80..143
    int tid = threadIdx.x;
    float s1 = 0.f, s2 = 0.f;
    for (int i = tid; i < BB * NN; i += 256) {
        int b = i >> 10, n = i & 1023;
        float v = g_proj[(b * OCH + src) * NN + n];
        s1 += v; s2 += v * v;
    }
    __shared__ float r1[256], r2[256];
    r1[tid] = s1; r2[tid] = s2;
    __syncthreads();
    for (int s = 128; s > 0; s >>= 1) {
        if (tid < s) { r1[tid] += r1[tid + s]; r2[tid] += r2[tid + s]; }
        __syncthreads();
    }
    if (tid == 0) {
        const float inv = 1.0f / (BB * NN);
        float mean = r1[0] * inv;
        float var  = r2[0] * inv - mean * mean;
        float w  = (ch < 64) ? bnqw[ch] : bnvw[ch - 64];
        float bi = (ch < 64) ? bnqb[ch] : bnvb[ch - 64];
        float sc = w * rsqrtf(var + EPSBN);
        g_scale[ch] = sc;
        g_shift[ch] = bi - mean * sc;
    }
}

// ================= kernel 3: softmax over n per (b,k) =================
__global__ __launch_bounds__(256) void softmax_kernel() {
    int row = blockIdx.x;                      // 0..511
    int b = row >> 4, k = row & 15;
    const float* src = g_proj + (b * OCH + 64 + k) * NN;
    int tid = threadIdx.x;
    float v[4];
    #pragma unroll
    for (int j = 0; j < 4; j++) v[j] = src[tid + 256 * j];
    float m = fmaxf(fmaxf(v[0], v[1]), fmaxf(v[2], v[3]));
    __shared__ float red[256];
    red[tid] = m; __syncthreads();
    for (int s = 128; s > 0; s >>= 1) {
        if (tid < s) red[tid] = fmaxf(red[tid], red[tid + s]);
        __syncthreads();
    }
    m = red[0];
    __syncthreads();
    float e[4], loc = 0.f;
    #pragma unroll
    for (int j = 0; j < 4; j++) { e[j] = expf(v[j] - m); loc += e[j]; }
    red[tid] = loc; __syncthreads();
    for (int s = 128; s > 0; s >>= 1) {
        if (tid < s) red[tid] += red[tid + s];
        __syncthreads();
    }
    float inv = 1.0f / red[0];
    float* dst = g_soft + (b * KD + k) * NN;
    #pragma unroll
    for (int j = 0; j < 4; j++) dst[tid + 256 * j] = e[j] * inv;
}

// ================= kernel 4: normalize q, normalize+pad v =================
__global__ __launch_bounds__(256) void normpad_kernel() {
    int ch = blockIdx.x, b = blockIdx.y, tid = threadIdx.x;
    float qs = g_scale[ch], qh = g_shift[ch];
    const float* qsrc = g_proj + (b * OCH + ch) * NN;
    float* qdst = g_qbn + (b * 64 + ch) * NN;
    for (int n = tid; n < NN; n += 256) qdst[n] = qsrc[n] * qs + qh;

    float vs = g_scale[64 + ch], vh = g_shift[64 + ch];
    const float* vsrc = g_proj + (b * OCH + 80 + ch) * NN;
    float* vdst = g_vpad + (b * 64 + ch) * PIMG;
    for (int i = tid; i < PIMG; i += 256) {
        int rr = i / PS, cc = i % PS;
        float val = 0.f;
        if (rr >= PADR && rr < PADR + 32 && cc >= PADR && cc < PADR + 32)
            val = vsrc[(rr - PADR) * 32 + (cc - PADR)] * vs + vh;
        vdst[i] = val;
    }
}

// ================= kernel 5: lambda_c[b,k,v] = sum_n soft * v_bn =================
__global__ __launch_bounds__(256) void lambdac_kernel() {
    int b = blockIdx.x, tid = threadIdx.x;
    int v = tid & 63;
    int kg = tid >> 6;                         // 0..3; covers k = kg + 4a
    __shared__ float ss[16][128];
    __shared__ float vsm[64][129];
    float acc[4] = {0.f, 0.f, 0.f, 0.f};
    for (int nc = 0; nc < 8; nc++) {
        int n0 = nc * 128;
        #pragma unroll
        for (int j = 0; j < 8; j++) {
            int f = tid + 256 * j;
            int k = f >> 7, n = f & 127;
            ss[k][n] = g_soft[(b * KD + k) * NN + n0 + n];
        }
        #pragma unroll
        for (int j = 0; j < 32; j++) {
            int f = tid + 256 * j;
            int vv = f >> 7, n = f & 127;
            int nn = n0 + n;
            vsm[vv][n] = g_vpad[(b * 64 + vv) * PIMG + ((nn >> 5) + PADR) * PS + (nn & 31) + PADR];
        }
        __syncthreads();
        for (int n = 0; n < 128; n++) {
            float vx = vsm[v][n];
            #pragma unroll
            for (int a = 0; a < 4; a++) acc[a] = fmaf(ss[kg + 4 * a][n], vx, acc[a]);
        }
        __syncthreads();
    }
    #pragma unroll
    for (int a = 0; a < 4; a++) g_lc[(b * KD + kg + 4 * a) * VV + v] = acc[a];
}

// ================= kernel 6: stage A — Qtilde[b,h,o,n] = sum_k q[b,h,k,n] * w[k,o] ===
// grid (4 n-chunks, 128 bh), 256 threads; thread owns one n.
__global__ __launch_bounds__(256) void qtilde_kernel(const float* __restrict__ emb) {
    __shared__ float ws[16][532];              // 34048 B, rows 16B-aligned
    int bh = blockIdx.y;                       // b*4 + h
    int b = bh >> 2, h = bh & 3;
    int t = threadIdx.x;
    int n = blockIdx.x * 256 + t;

    for (int idx = t; idx < 16 * OFFS; idx += 256) {
        int k = idx / OFFS, o = idx - k * OFFS;
        ws[k][o] = emb[k * OFFS + o];
    }

    u64 qd[16];
    #pragma unroll
    for (int k = 0; k < 16; k++) {
        float qv = g_qbn[(b * 64 + h * 16 + k) * NN + n];
        qd[k] = pack2s(qv);
    }
    __syncthreads();

    float* dst = g_qt + (size_t)bh * OFFS * NN + n;
    for (int ob = 0; ob < 528; ob += 8) {
        u64 a0 = 0ull, a1 = 0ull, a2 = 0ull, a3 = 0ull;
        #pragma unroll
        for (int k = 0; k < 16; k++) {
            ulonglong2 wA = *reinterpret_cast<const ulonglong2*>(&ws[k][ob]);
            ulonglong2 wB = *reinterpret_cast<const ulonglong2*>(&ws[k][ob + 4]);
            fma2(a0, wA.x, qd[k]);
            fma2(a1, wA.y, qd[k]);
            fma2(a2, wB.x, qd[k]);
            fma2(a3, wB.y, qd[k]);
        }
        float l0, h0, l1, h1, l2, h2, l3, h3;
        unpack2(a0, l0, h0); unpack2(a1, l1, h1);
        unpack2(a2, l2, h2); unpack2(a3, l3, h3);
        dst[(size_t)(ob + 0) * NN] = l0; dst[(size_t)(ob + 1) * NN] = h0;
        dst[(size_t)(ob + 2) * NN] = l1; dst[(size_t)(ob + 3) * NN] = h1;
        dst[(size_t)(ob + 4) * NN] = l2; dst[(size_t)(ob + 5) * NN] = h2;
        dst[(size_t)(ob + 6) * NN] = l3; dst[(size_t)(ob + 7) * NN] = h3;
    }
    // leftover o = 528
    {
        float s = 0.f;
        #pragma unroll
        for (int k = 0; k < 16; k++) {
            float lo, hi;
            unpack2(qd[k], lo, hi); (void)hi;
            s = fmaf(ws[k][528], lo, s);
        }
        dst[(size_t)528 * NN] = s;
    }
}

// ================= kernel 7: stage B — y = (1+g)*(sum_o Qt*vpad + sum_k q*lc) ======
// grid (32 r, 32 b), 256 threads: c = t&31 (output col), vg = t>>5 (v-octet).
// acc[vi][hp]: packed over h-pairs (h=2hp, 2hp+1); v scalar loads from natural
// [v][col] layout (lane-contiguous in col -> conflict-free LDS).
__global__ __launch_bounds__(256) void stageB_kernel(const float* __restrict__ gamma,
                                                     float* __restrict__ out) {
    __shared__ float vrow[64 * 57];            // 14592 B: vpad row, [v][col] stride 57
    __shared__ u64   qsm[2][23][32];           // 11776 B: h-pair packed Qtilde
    __shared__ float lcs[16][64];              // 4096 B

    int r = blockIdx.x, b = blockIdx.y;
    int t = threadIdx.x;
    int c = t & 31, vg = t >> 5;

    u64 acc[8][2];
    #pragma unroll
    for (int i = 0; i < 8; i++) { acc[i][0] = 0ull; acc[i][1] = 0ull; }

    for (int dr = 0; dr < 23; dr++) {
        __syncthreads();
        // stage vpad row (r+dr), all 64 v: vrow[v*57 + col]
        int row = r + dr;
        const float* vsrc = g_vpad + (size_t)(b * 64) * PIMG + row * PS;
        #pragma unroll
        for (int j = 0; j < 16; j++) {
            int idx = t + j * 256;             // < 4096
            int v = idx >> 6, col = idx & 63;
            if (col < PS)
                vrow[v * 57 + col] = vsrc[(size_t)v * PIMG + col];
        }
        // stage Qtilde h-pairs: qsm[hp][dc][c] = (Qt[h=2hp], Qt[h=2hp+1]) at o=dr*23+dc
        #pragma unroll
        for (int j = 0; j < 6; j++) {
            int idx = t + j * 256;
            if (idx < 1472) {
                int cc = idx & 31, rest = idx >> 5;        // rest < 46
                int hp = rest / 23, dc = rest - hp * 23;
                size_t base = ((size_t)(b * 4 + 2 * hp) * OFFS + dr * 23 + dc) * NN + r * 32 + cc;
                float q0 = g_qt[base];
                float q1 = g_qt[base + (size_t)OFFS * NN];
                qsm[hp][dc][cc] = pack2(q0, q1);
            }
        }
        __syncthreads();
        #pragma unroll 1
        for (int dc = 0; dc < 23; dc++) {
            u64 qp0 = qsm[0][dc][c];
            u64 qp1 = qsm[1][dc][c];
            const float* vb = &vrow[(vg * 8) * 57 + c + dc];
            #pragma unroll
            for (int i = 0; i < 8; i++) {
                u64 vd = pack2s(vb[i * 57]);
                fma2(acc[i][0], qp0, vd);
                fma2(acc[i][1], qp1, vd);
            }
        }
    }

    // ---- epilogue: y_c = sum_k q[b, h*16+k, n] * lc[b,k,v], then scale+store ----
    __syncthreads();
    #pragma unroll
    for (int j = 0; j < 8; j++) {
        int idx = t + j * 256;                 // < 2048: qep[ch][c] in vrow buffer
        int ch = idx >> 5, cc = idx & 31;
        vrow[ch * 32 + cc] = g_qbn[(b * 64 + ch) * NN + r * 32 + cc];
    }
    #pragma unroll
    for (int j = 0; j < 4; j++) {
        int idx = t + j * 256;                 // < 1024
        lcs[idx >> 6][idx & 63] = g_lc[b * 1024 + idx];
    }
    __syncthreads();
    #pragma unroll
    for (int k = 0; k < 16; k++) {
        u64 qp0 = pack2(vrow[(0 * 16 + k) * 32 + c], vrow[(1 * 16 + k) * 32 + c]);
        u64 qp1 = pack2(vrow[(2 * 16 + k) * 32 + c], vrow[(3 * 16 + k) * 32 + c]);
        #pragma unroll
        for (int i = 0; i < 8; i++) {
            u64 ld = pack2s(lcs[k][vg * 8 + i]);
            fma2(acc[i][0], qp0, ld);
            fma2(acc[i][1], qp1, ld);
        }
    }

    float g1 = 1.0f + gamma[0];
    #pragma unroll
    for (int i = 0; i < 8; i++) {
        int v = vg * 8 + i;
        #pragma unroll
        for (int hp = 0; hp < 2; hp++) {
            float lo, hi;
            unpack2(acc[i][hp], lo, hi);
            size_t base = ((size_t)(b * 256) + (2 * hp) * 64 + v) * NN + r * 32 + c;
            out[base]           = g1 * lo;      // h = 2*hp
            out[base + 64 * NN] = g1 * hi;      // h = 2*hp+1
        }
    }
}

// ================= launch =================
extern "C" void kernel_launch(void* const* d_in, const int* in_sizes, int n_in,
                              void* d_out, int out_size) {
    (void)in_sizes; (void)n_in; (void)out_size;
    const float* x    = (const float*)d_in[0];
    const float* Wq   = (const float*)d_in[1];
    const float* bnqw = (const float*)d_in[2];
    const float* bnqb = (const float*)d_in[3];
    const float* Wk   = (const float*)d_in[4];
    const float* Wv   = (const float*)d_in[5];
    const float* bnvw = (const float*)d_in[6];
    const float* bnvb = (const float*)d_in[7];
    const float* emb  = (const float*)d_in[8];
    const float* gam  = (const float*)d_in[9];
    float* out = (float*)d_out;

    pack_kernel<<<32, 256>>>(Wq, Wk, Wv);
    proj_kernel<<<dim3(8, 32), 256>>>(x);
    bnstats_kernel<<<128, 256>>>(bnqw, bnqb, bnvw, bnvb);
    softmax_kernel<<<512, 256>>>();
    normpad_kernel<<<dim3(64, 32), 256>>>();
    lambdac_kernel<<<32, 256>>>();
    qtilde_kernel<<<dim3(4, 128), 256>>>(emb);
    stageB_kernel<<<dim3(32, 32), 256>>>(gam, out);
}